// round 3
// baseline (speedup 1.0000x reference)
#include <cuda_runtime.h>
#include <cstdint>

// LIF neuron scan: v = 0.5*v + x_t; spike = (v >= 1); v = spike ? 0 : v
// x: [T, B, D] f32, v0: [D] f32, out spikes: [T, B, D] f32.
//
// R3: register-resident prefetch ring (DEPTH=8 float4/thread) with streaming
// LDG.128/STG.128 (__ldcs/__stcs), replacing the cp.async SMEM ring. Cuts
// per-step LSU issue from ~96 to ~64 cyc/SM (LDGSTS+LDS+STG -> LDG+STG) while
// keeping 2.4 MB chip-wide reads in flight (>2x BW*latency requirement).

#define LIF_CTA   128
#define LIF_GRID  148
#define LIF_DEPTH 8
#define LIF_TAU   0.5f

__global__ void __launch_bounds__(LIF_CTA, 1)
lif_scan_kernel(const float* __restrict__ x,
                const float* __restrict__ v0,
                float* __restrict__ out,
                int T, int N4, int D4, int chunk)
{
    const int chain = blockIdx.x * chunk + threadIdx.x;
    if (threadIdx.x >= chunk || chain >= N4) return;

    const float4* gp = (const float4*)x + chain;   // read cursor
    float4*       op = (float4*)out + chain;       // write cursor
    const int stride = N4;                          // float4s per timestep

    // ---- prologue: fill DEPTH-deep register ring ----
    float4 buf[LIF_DEPTH];
    #pragma unroll
    for (int s = 0; s < LIF_DEPTH; s++) {
        buf[s] = __ldcs(gp);
        gp += stride;
    }

    // initial membrane potential: v0[d] broadcast over batch
    float4 v = ((const float4*)v0)[chain % D4];

    const int steady = T - LIF_DEPTH;   // 504 for T=512; 504 % 8 == 0

    // ---- steady state: consume slot s, immediately refill it ----
    for (int t = 0; t < steady; t += LIF_DEPTH) {
        #pragma unroll
        for (int s = 0; s < LIF_DEPTH; s++) {
            float4 xt = buf[s];
            buf[s] = __ldcs(gp);
            gp += stride;

            float4 sp;
            v.x = fmaf(LIF_TAU, v.x, xt.x);
            v.y = fmaf(LIF_TAU, v.y, xt.y);
            v.z = fmaf(LIF_TAU, v.z, xt.z);
            v.w = fmaf(LIF_TAU, v.w, xt.w);
            bool fx = v.x >= 1.0f, fy = v.y >= 1.0f,
                 fz = v.z >= 1.0f, fw = v.w >= 1.0f;
            sp.x = fx ? 1.0f : 0.0f;  v.x = fx ? 0.0f : v.x;
            sp.y = fy ? 1.0f : 0.0f;  v.y = fy ? 0.0f : v.y;
            sp.z = fz ? 1.0f : 0.0f;  v.z = fz ? 0.0f : v.z;
            sp.w = fw ? 1.0f : 0.0f;  v.w = fw ? 0.0f : v.w;

            __stcs(op, sp);
            op += stride;
        }
    }

    // ---- drain: last DEPTH timesteps, no more loads ----
    #pragma unroll
    for (int s = 0; s < LIF_DEPTH; s++) {
        float4 xt = buf[s];
        float4 sp;
        v.x = fmaf(LIF_TAU, v.x, xt.x);
        v.y = fmaf(LIF_TAU, v.y, xt.y);
        v.z = fmaf(LIF_TAU, v.z, xt.z);
        v.w = fmaf(LIF_TAU, v.w, xt.w);
        bool fx = v.x >= 1.0f, fy = v.y >= 1.0f,
             fz = v.z >= 1.0f, fw = v.w >= 1.0f;
        sp.x = fx ? 1.0f : 0.0f;  v.x = fx ? 0.0f : v.x;
        sp.y = fy ? 1.0f : 0.0f;  v.y = fy ? 0.0f : v.y;
        sp.z = fz ? 1.0f : 0.0f;  v.z = fz ? 0.0f : v.z;
        sp.w = fw ? 1.0f : 0.0f;  v.w = fw ? 0.0f : v.w;
        __stcs(op, sp);
        op += stride;
    }
}

extern "C" void kernel_launch(void* const* d_in, const int* in_sizes, int n_in,
                              void* d_out, int out_size)
{
    const float* x  = (const float*)d_in[0];   // [T, B, D]
    const float* v0 = (const float*)d_in[1];   // [D]
    float* out = (float*)d_out;

    const int T = 512;                 // fixed by problem setup
    const int total = in_sizes[0];     // T*B*D
    const int D = in_sizes[1];
    const int N  = total / T;          // B*D
    const int N4 = N / 4;
    const int D4 = D / 4;

    // Spread chains over all 148 SMs; chains per CTA capped at CTA size.
    int chunk = (N4 + LIF_GRID - 1) / LIF_GRID;
    if (chunk > LIF_CTA) chunk = LIF_CTA;
    int grid = (N4 + chunk - 1) / chunk;

    lif_scan_kernel<<<grid, LIF_CTA>>>(x, v0, out, T, N4, D4, chunk);
}

// round 4
// speedup vs baseline: 1.5511x; 1.5511x over previous
#include <cuda_runtime.h>
#include <cstdint>

// LIF neuron scan: v = 0.5*v + x_t; spike = (v >= 1); v = spike ? 0 : v
// x: [T, B, D] f32, v0: [D] f32, out spikes: [T, B, D] f32.
//
// Structure = R2 winner (24-stage per-thread cp.async SMEM ring, no
// __syncthreads, positional wait_group ordering). R4 deltas:
//  - commit groups of 4 loads (6 groups x 4 stages), wait_group 5 -> 20-step
//    slack, 4x fewer commit/wait instructions
//  - reads carry L2::evict_first cache policy (read-once stream)
//  - stores use __stcs (write-once stream, evict-first dirty lines)

#define LIF_CTA    128
#define LIF_GRID   148
#define LIF_STAGES 24            // ring slots (16B each per thread) = 48 KB smem
#define LIF_BATCH  4             // loads per commit group
#define LIF_GROUPS (LIF_STAGES / LIF_BATCH)   // 6
#define LIF_TAU    0.5f

__global__ void __launch_bounds__(LIF_CTA, 1)
lif_scan_kernel(const float* __restrict__ x,
                const float* __restrict__ v0,
                float* __restrict__ out,
                int T, int N4, int D4, int chunk)
{
    __shared__ float4 ring[LIF_STAGES][LIF_CTA];

    const int chain = blockIdx.x * chunk + threadIdx.x;
    if (threadIdx.x >= chunk || chain >= N4) return;

    uint32_t slot0 = (uint32_t)__cvta_generic_to_shared(&ring[0][threadIdx.x]);
    const uint32_t stage_bytes = LIF_CTA * 16u;

    const char* gp = (const char*)x + (size_t)chain * 16u;
    const size_t gstride = (size_t)N4 * 16u;     // bytes per timestep

    // L2 evict-first policy for the read-once input stream
    uint64_t pol;
    asm volatile("createpolicy.fractional.L2::evict_first.b64 %0, 1.0;\n"
                 : "=l"(pol));

    // ---- prologue: fill GROUPS-1 = 5 groups (20 stages) ----
    #pragma unroll
    for (int g = 0; g < LIF_GROUPS - 1; g++) {
        #pragma unroll
        for (int j = 0; j < LIF_BATCH; j++) {
            uint32_t dst = slot0 + (uint32_t)(g * LIF_BATCH + j) * stage_bytes;
            asm volatile(
                "cp.async.cg.shared.global.L2::cache_hint [%0], [%1], 16, %2;\n"
                :: "r"(dst), "l"(gp), "l"(pol) : "memory");
            gp += gstride;
        }
        asm volatile("cp.async.commit_group;\n" ::: "memory");
    }

    // initial membrane potential: v0[d] broadcast over batch
    float4 v = ((const float4*)v0)[chain % D4];

    float4* op = (float4*)out + chain;

    int wgrp = LIF_GROUPS - 1;   // ring group to write next
    int rslot = 0;               // stage slot to read next

    const int prefetched = (LIF_GROUPS - 1) * LIF_BATCH;   // 20 steps in flight

    for (int t = 0; t < T; t += LIF_BATCH) {
        // issue the group for steps t+20..t+23 (if any); ALWAYS commit one
        // group per iteration so positional wait_group accounting holds
        if (t + prefetched < T) {
            #pragma unroll
            for (int j = 0; j < LIF_BATCH; j++) {
                uint32_t dst = slot0 +
                    (uint32_t)(wgrp * LIF_BATCH + j) * stage_bytes;
                asm volatile(
                    "cp.async.cg.shared.global.L2::cache_hint [%0], [%1], 16, %2;\n"
                    :: "r"(dst), "l"(gp), "l"(pol) : "memory");
                gp += gstride;
            }
        }
        asm volatile("cp.async.commit_group;\n" ::: "memory");
        if (++wgrp == LIF_GROUPS) wgrp = 0;

        // all but the 5 most recent groups complete -> this batch's data landed
        asm volatile("cp.async.wait_group %0;\n" :: "n"(LIF_GROUPS - 1) : "memory");

        #pragma unroll
        for (int j = 0; j < LIF_BATCH; j++) {
            float4 xt;
            uint32_t src = slot0 + (uint32_t)rslot * stage_bytes;
            asm volatile("ld.shared.v4.f32 {%0,%1,%2,%3}, [%4];\n"
                         : "=f"(xt.x), "=f"(xt.y), "=f"(xt.z), "=f"(xt.w)
                         : "r"(src));
            if (++rslot == LIF_STAGES) rslot = 0;

            float4 sp;
            v.x = fmaf(LIF_TAU, v.x, xt.x);
            v.y = fmaf(LIF_TAU, v.y, xt.y);
            v.z = fmaf(LIF_TAU, v.z, xt.z);
            v.w = fmaf(LIF_TAU, v.w, xt.w);
            bool fx = v.x >= 1.0f, fy = v.y >= 1.0f,
                 fz = v.z >= 1.0f, fw = v.w >= 1.0f;
            sp.x = fx ? 1.0f : 0.0f;  v.x = fx ? 0.0f : v.x;
            sp.y = fy ? 1.0f : 0.0f;  v.y = fy ? 0.0f : v.y;
            sp.z = fz ? 1.0f : 0.0f;  v.z = fz ? 0.0f : v.z;
            sp.w = fw ? 1.0f : 0.0f;  v.w = fw ? 0.0f : v.w;

            __stcs(op, sp);
            op += N4;
        }
    }
}

extern "C" void kernel_launch(void* const* d_in, const int* in_sizes, int n_in,
                              void* d_out, int out_size)
{
    const float* x  = (const float*)d_in[0];   // [T, B, D]
    const float* v0 = (const float*)d_in[1];   // [D]
    float* out = (float*)d_out;

    const int T = 512;                 // fixed by problem setup
    const int total = in_sizes[0];     // T*B*D
    const int D = in_sizes[1];
    const int N  = total / T;          // B*D
    const int N4 = N / 4;
    const int D4 = D / 4;

    // Spread chains over all 148 SMs; chains per CTA capped at CTA size.
    int chunk = (N4 + LIF_GRID - 1) / LIF_GRID;
    if (chunk > LIF_CTA) chunk = LIF_CTA;
    int grid = (N4 + chunk - 1) / chunk;

    lif_scan_kernel<<<grid, LIF_CTA>>>(x, v0, out, T, N4, D4, chunk);
}